// round 7
// baseline (speedup 1.0000x reference)
#include <cuda_runtime.h>
#include <cstdint>
#include <cstddef>

#define NBLK  148
#define BATCH 64
#define PP    196
#define ENCD  512
#define DECD  512
#define EMBD  256
#define ATTD  128
#define FFND  1024
#define VOCAB 2000
#define TT    159
#define MAXL  160
#define GIND  768
#define EPSV  1e-5f

// output: float32 concat of (preds[B,T,V], caps[B,160], dec_lens[B], alphas[B,T,P], order[B])
#define OP_OFF 0ull
#define OC_OFF 20352000ull
#define OL_OFF 20362240ull
#define OA_OFF 20362304ull
#define OO_OFF 22356800ull

// ---------------- device scratch ----------------
__device__ float g_att1[BATCH * PP * ATTD];
__device__ float g_h1[BATCH * DECD];
__device__ float g_h2[BATCH * DECD];
__device__ float g_h1res[BATCH * DECD];
__device__ float g_h2res[BATCH * DECD];
__device__ float g_gin[BATCH * GIND];
__device__ float p_gi1[3 * BATCH * 1536];
__device__ float p_gh1[2 * BATCH * 1536];
__device__ float p_proj[3 * BATCH * DECD];
__device__ float p_gi2[2 * BATCH * 1536];
__device__ float p_gh2[2 * BATCH * 1536];
__device__ float p_f1[2 * BATCH * FFND];
__device__ float p_f2[2 * BATCH * VOCAB];
__device__ unsigned g_bcnt;
__device__ volatile unsigned g_bsense;

struct Params {
    const float* enc;  const int* caps;  const int* lens;
    const float *eaw, *eab, *daw, *dab, *faw, *fab;
    const float *gw1, *gb1, *gw2, *gb2, *emb;
    const float *g1wih, *g1whh, *g1bih, *g1bhh;
    const float *g2wih, *g2whh, *g2bih, *g2bhh;
    const float *pw, *pb, *ln1g, *ln1b, *ln2g, *ln2b;
    const float *fw1, *fb1, *fw2, *fb2;
    float* out;
};

struct SmemG { float Xs[2][16][68]; float Ws[2][16][36]; };
struct SmemA { float h2s[DECD]; float att2s[ATTD]; float ggs[ATTD]; float alpha[PP]; float red[32]; };
union SmemU { SmemG g; SmemA a; };

// ---------------- grid barrier (sense-reversing; 148 co-resident CTAs) ----------------
__device__ __forceinline__ void gsync(unsigned& ls) {
    __syncthreads();
    if (threadIdx.x == 0) {
        ls ^= 1u;
        __threadfence();
        if (atomicAdd(&g_bcnt, 1u) == NBLK - 1u) {
            g_bcnt = 0u;
            __threadfence();
            g_bsense = ls;
        } else {
            while (g_bsense != ls) __nanosleep(64);
        }
        __threadfence();
    }
    __syncthreads();
}

// ---------------- block reductions (256 threads) ----------------
__device__ __forceinline__ float block_sum(float v, float* buf) {
    int lane = threadIdx.x & 31, w = threadIdx.x >> 5;
#pragma unroll
    for (int o = 16; o; o >>= 1) v += __shfl_down_sync(0xffffffffu, v, o);
    if (!lane) buf[w] = v;
    __syncthreads();
    if (threadIdx.x == 0) {
        float s = buf[0];
#pragma unroll
        for (int i = 1; i < 8; i++) s += buf[i];
        buf[0] = s;
    }
    __syncthreads();
    float r = buf[0];
    __syncthreads();
    return r;
}

__device__ __forceinline__ float block_max(float v, float* buf) {
    int lane = threadIdx.x & 31, w = threadIdx.x >> 5;
#pragma unroll
    for (int o = 16; o; o >>= 1) v = fmaxf(v, __shfl_down_sync(0xffffffffu, v, o));
    if (!lane) buf[w] = v;
    __syncthreads();
    if (threadIdx.x == 0) {
        float s = buf[0];
#pragma unroll
        for (int i = 1; i < 8; i++) s = fmaxf(s, buf[i]);
        buf[0] = s;
    }
    __syncthreads();
    float r = buf[0];
    __syncthreads();
    return r;
}

__device__ __forceinline__ float sigm(float x) { return 1.f / (1.f + expf(-x)); }

// ---------------- GEMM tile: C[64 x 32] += X[64 x Kc] @ W[N x K]^T slice ----------------
// BM=64, BN=32, BK=16, 256 threads, 4x2 per thread, double-buffered smem.
// comb mode (X2 != null): X element = relu(X + X2 + xb[k]).
__device__ void gemm_tile(const float* __restrict__ X, const float* __restrict__ X2,
                          const float* __restrict__ xb, int ldX,
                          const float* __restrict__ W, int ldW,
                          const float* __restrict__ bias,
                          float* __restrict__ C, int ldC, int N,
                          int mbase, int nbase, int k0, int nk, SmemG* sg) {
    const int tid = threadIdx.x;
    const int lm  = tid >> 2;
    const int lk4 = (tid & 3) << 2;
    const int ln  = tid >> 3;
    const int lk2 = (tid & 7) << 1;
    const int tx  = (tid & 15) << 2;
    const int ty  = (tid >> 4) << 1;

    const bool comb = (X2 != nullptr);
    const float* Xp  = X + (size_t)(mbase + lm) * ldX + k0 + lk4;
    const float* X2p = comb ? X2 + (size_t)(mbase + lm) * ldX + k0 + lk4 : nullptr;
    const int gnw = nbase + ln;
    const bool wok = gnw < N;
    const float* Wp = W + (size_t)gnw * ldW + k0 + lk2;

    float4 xr = *(const float4*)Xp;
    if (comb) {
        float4 x2 = *(const float4*)X2p;
        const float* bb = xb + k0 + lk4;
        xr.x = fmaxf(xr.x + x2.x + bb[0], 0.f);
        xr.y = fmaxf(xr.y + x2.y + bb[1], 0.f);
        xr.z = fmaxf(xr.z + x2.z + bb[2], 0.f);
        xr.w = fmaxf(xr.w + x2.w + bb[3], 0.f);
    }
    float2 wr = wok ? *(const float2*)Wp : make_float2(0.f, 0.f);

    __syncthreads();   // protect smem vs previous tile / phase
    sg->Xs[0][lk4 + 0][lm] = xr.x;
    sg->Xs[0][lk4 + 1][lm] = xr.y;
    sg->Xs[0][lk4 + 2][lm] = xr.z;
    sg->Xs[0][lk4 + 3][lm] = xr.w;
    sg->Ws[0][lk2 + 0][ln] = wr.x;
    sg->Ws[0][lk2 + 1][ln] = wr.y;

    float acc[4][2] = {};
    int buf = 0;
    for (int kt = 0; kt < nk; kt++) {
        if (kt + 1 < nk) {
            xr = *(const float4*)(Xp + (kt + 1) * 16);
            if (comb) {
                float4 x2 = *(const float4*)(X2p + (kt + 1) * 16);
                const float* bb = xb + k0 + (kt + 1) * 16 + lk4;
                xr.x = fmaxf(xr.x + x2.x + bb[0], 0.f);
                xr.y = fmaxf(xr.y + x2.y + bb[1], 0.f);
                xr.z = fmaxf(xr.z + x2.z + bb[2], 0.f);
                xr.w = fmaxf(xr.w + x2.w + bb[3], 0.f);
            }
            wr = wok ? *(const float2*)(Wp + (kt + 1) * 16) : make_float2(0.f, 0.f);
        }
        __syncthreads();
#pragma unroll
        for (int kk = 0; kk < 16; kk++) {
            const float4 a = *(const float4*)&sg->Xs[buf][kk][tx];
            const float2 b = *(const float2*)&sg->Ws[buf][kk][ty];
            acc[0][0] = fmaf(a.x, b.x, acc[0][0]); acc[0][1] = fmaf(a.x, b.y, acc[0][1]);
            acc[1][0] = fmaf(a.y, b.x, acc[1][0]); acc[1][1] = fmaf(a.y, b.y, acc[1][1]);
            acc[2][0] = fmaf(a.z, b.x, acc[2][0]); acc[2][1] = fmaf(a.z, b.y, acc[2][1]);
            acc[3][0] = fmaf(a.w, b.x, acc[3][0]); acc[3][1] = fmaf(a.w, b.y, acc[3][1]);
        }
        if (kt + 1 < nk) {
            int nb = buf ^ 1;
            sg->Xs[nb][lk4 + 0][lm] = xr.x;
            sg->Xs[nb][lk4 + 1][lm] = xr.y;
            sg->Xs[nb][lk4 + 2][lm] = xr.z;
            sg->Xs[nb][lk4 + 3][lm] = xr.w;
            sg->Ws[nb][lk2 + 0][ln] = wr.x;
            sg->Ws[nb][lk2 + 1][ln] = wr.y;
            buf = nb;
        }
    }
#pragma unroll
    for (int i = 0; i < 4; i++) {
        int gm = mbase + tx + i;
#pragma unroll
        for (int j = 0; j < 2; j++) {
            int gn = nbase + ty + j;
            if (gn < N)
                C[(size_t)gm * ldC + gn] = acc[i][j] + (bias ? bias[gn] : 0.f);
        }
    }
}

// ---------------- the single persistent kernel ----------------
__global__ void __launch_bounds__(256) decoder_persist(Params P) {
    __shared__ SmemU su;
    __shared__ int s_ord[BATCH];
    __shared__ int s_dl[BATCH];

    const int tid = threadIdx.x;
    const int bid = blockIdx.x;
    unsigned ls = g_bsense;

    // ---- every block computes the stable descending argsort locally ----
    if (tid < BATCH) {
        int Li = P.lens[tid];
        int r = 0;
        for (int j = 0; j < BATCH; j++) {
            int Lj = P.lens[j];
            r += (Lj > Li) || (Lj == Li && j < tid);
        }
        s_ord[r] = tid;
        s_dl[r]  = Li - 1;
    }
    __syncthreads();

    // ---- static outputs + state init ----
    if (bid == 0) {
        if (tid < BATCH) {
            P.out[OL_OFF + tid] = (float)s_dl[tid];
            P.out[OO_OFF + tid] = (float)s_ord[tid];
        }
        for (int i = tid; i < BATCH * MAXL; i += 256)
            P.out[OC_OFF + i] = (float)P.caps[s_ord[i / MAXL] * MAXL + (i % MAXL)];
    }
    if (bid < BATCH) {
        for (int i = tid; i < DECD; i += 256) {
            g_h1[bid * DECD + i] = 0.f;
            g_h2[bid * DECD + i] = 0.f;
        }
    }

    // ---- att1 = enc @ enc_att_w^T + b, in ORIGINAL batch order (no reorder needed) ----
    for (int tl = bid; tl < PP * 4; tl += NBLK) {
        int mt = tl >> 2, nt = tl & 3;
        gemm_tile(P.enc, nullptr, nullptr, ENCD, P.eaw, ENCD, P.eab,
                  g_att1, ATTD, ATTD, mt * 64, nt * 32, 0, 32, &su.g);
    }
    gsync(ls);

    for (int t = 0; t < TT; t++) {
        // ======== phase 1: attention (blocks 0..63) + pred-write t-1 (blocks 64..147)
        if (bid < BATCH) {
            const int b = bid;
            const int ob = s_ord[b];
            SmemA* A = &su.a;
            for (int i = tid; i < DECD; i += 256) A->h2s[i] = g_h2[b * DECD + i];
            __syncthreads();
            const int lane = tid & 31, w = tid >> 5;
            for (int r = 0; r < 16; r++) {
                int i = w * 16 + r;
                const float* wr_ = P.daw + (size_t)i * DECD;
                const float* gr_ = P.gw1 + (size_t)i * DECD;
                float s1 = 0.f, s2 = 0.f;
                for (int k = lane; k < DECD; k += 32) {
                    float h = A->h2s[k];
                    s1 += wr_[k] * h;
                    s2 += gr_[k] * h;
                }
#pragma unroll
                for (int o = 16; o; o >>= 1) {
                    s1 += __shfl_down_sync(0xffffffffu, s1, o);
                    s2 += __shfl_down_sync(0xffffffffu, s2, o);
                }
                if (!lane) {
                    A->att2s[i] = s1 + P.dab[i];
                    A->ggs[i]   = fmaxf(s2 + P.gb1[i], 0.f);
                }
            }
            __syncthreads();
            float gv = (tid < ATTD) ? A->ggs[tid] * P.gw2[tid] : 0.f;
            float gate = sigm(block_sum(gv, A->red) + P.gb2[0]);

            float e = -1e30f;
            if (tid < PP) {
                const float* a1 = g_att1 + (size_t)(ob * PP + tid) * ATTD;
                float s = 0.f;
#pragma unroll 4
                for (int a = 0; a < ATTD; a++) s += P.faw[a] * fmaxf(a1[a] + A->att2s[a], 0.f);
                e = s + P.fab[0];
            }
            float mx  = block_max(e, A->red);
            float ev  = (tid < PP) ? expf(e - mx) : 0.f;
            float inv = 1.f / block_sum(ev, A->red);
            float mt_ = (t < s_dl[b]) ? 1.f : 0.f;
            if (tid < PP) {
                float al = ev * inv;
                A->alpha[tid] = al;
                P.out[OA_OFF + ((size_t)b * TT + t) * PP + tid] = al * mt_;
            }
            __syncthreads();
            float aw0 = 0.f, aw1 = 0.f;
            const int c0 = tid * 2;
            const float* eb = P.enc + (size_t)ob * PP * ENCD + c0;
            for (int p = 0; p < PP; p++) {
                float al = A->alpha[p];
                float2 v = *(const float2*)(eb + (size_t)p * ENCD);
                aw0 += v.x * al;
                aw1 += v.y * al;
            }
            float* gin = g_gin + b * GIND;
            int cap = P.caps[ob * MAXL + t];
            gin[tid] = P.emb[(size_t)cap * EMBD + tid];   // 256 threads == EMBD
            gin[EMBD + c0]     = aw0 * gate;
            gin[EMBD + c0 + 1] = aw1 * gate;
        } else if (t > 0) {
            for (int i = (bid - BATCH) * 256 + tid; i < BATCH * VOCAB; i += (NBLK - BATCH) * 256) {
                int b = i / VOCAB, n = i - b * VOCAB;
                float m = ((t - 1) < s_dl[b]) ? 1.f : 0.f;
                P.out[OP_OFF + ((size_t)b * TT + (t - 1)) * VOCAB + n] =
                    (p_f2[b * VOCAB + n] + p_f2[BATCH * VOCAB + b * VOCAB + n] + P.fb2[n]) * m;
            }
        }
        gsync(ls);

        // ======== phase 2: gi1 (144 tiles) + gh1 (96) + proj (48) = 288 tiles
        for (int tl = bid; tl < 288; tl += NBLK) {
            if (tl < 144) {
                int nt = tl / 3, kc = tl % 3;
                gemm_tile(g_gin, nullptr, nullptr, GIND, P.g1wih, GIND, nullptr,
                          p_gi1 + kc * BATCH * 1536, 1536, 1536, 0, nt * 32, kc * 256, 16, &su.g);
            } else if (tl < 240) {
                int u = tl - 144, nt = u >> 1, kc = u & 1;
                gemm_tile(g_h1, nullptr, nullptr, DECD, P.g1whh, DECD, nullptr,
                          p_gh1 + kc * BATCH * 1536, 1536, 1536, 0, nt * 32, kc * 256, 16, &su.g);
            } else {
                int u = tl - 240, nt = u / 3, kc = u % 3;
                gemm_tile(g_gin, nullptr, nullptr, GIND, P.pw, GIND, nullptr,
                          p_proj + kc * BATCH * DECD, DECD, DECD, 0, nt * 32, kc * 256, 16, &su.g);
            }
        }
        gsync(ls);

        // ======== phase 3: gru1 + proj-add + LN1 + masked h1 update
        if (bid < BATCH) {
            const int b = bid;
            const float mt_ = (t < s_dl[b]) ? 1.f : 0.f;
            float pre[2], s = 0.f, s2 = 0.f;
#pragma unroll
            for (int j = 0; j < 2; j++) {
                int i = tid + j * 256;
                int o = b * 1536 + i;
                float gir = p_gi1[o] + p_gi1[BATCH * 1536 + o] + p_gi1[2 * BATCH * 1536 + o] + P.g1bih[i];
                float giz = p_gi1[o + 512] + p_gi1[BATCH * 1536 + o + 512] + p_gi1[2 * BATCH * 1536 + o + 512] + P.g1bih[i + 512];
                float gnn = p_gi1[o + 1024] + p_gi1[BATCH * 1536 + o + 1024] + p_gi1[2 * BATCH * 1536 + o + 1024] + P.g1bih[i + 1024];
                float ghr = p_gh1[o] + p_gh1[BATCH * 1536 + o] + P.g1bhh[i];
                float ghz = p_gh1[o + 512] + p_gh1[BATCH * 1536 + o + 512] + P.g1bhh[i + 512];
                float ghn = p_gh1[o + 1024] + p_gh1[BATCH * 1536 + o + 1024] + P.g1bhh[i + 1024];
                float r = sigm(gir + ghr), z = sigm(giz + ghz);
                float n = tanhf(gnn + r * ghn);
                int po = b * DECD + i;
                float ho = g_h1[po];
                float hn = (1.f - z) * n + z * ho;
                float pr = hn + p_proj[po] + p_proj[BATCH * DECD + po] + p_proj[2 * BATCH * DECD + po] + P.pb[i];
                pre[j] = pr;
                s += pr; s2 += pr * pr;
                g_h1[po] = (mt_ > 0.f) ? hn : ho;
            }
            float sum  = block_sum(s, su.a.red);
            float sum2 = block_sum(s2, su.a.red);
            float mean = sum * (1.f / 512.f);
            float var  = sum2 * (1.f / 512.f) - mean * mean;
            float inv  = rsqrtf(var + EPSV);
#pragma unroll
            for (int j = 0; j < 2; j++) {
                int i = tid + j * 256;
                g_h1res[b * DECD + i] = (pre[j] - mean) * inv * P.ln1g[i] + P.ln1b[i];
            }
        }
        gsync(ls);

        // ======== phase 4: gi2 (96 tiles) + gh2 (96) = 192 tiles
        for (int tl = bid; tl < 192; tl += NBLK) {
            if (tl < 96) {
                int nt = tl >> 1, kc = tl & 1;
                gemm_tile(g_h1res, nullptr, nullptr, DECD, P.g2wih, DECD, nullptr,
                          p_gi2 + kc * BATCH * 1536, 1536, 1536, 0, nt * 32, kc * 256, 16, &su.g);
            } else {
                int u = tl - 96, nt = u >> 1, kc = u & 1;
                gemm_tile(g_h2, nullptr, nullptr, DECD, P.g2whh, DECD, nullptr,
                          p_gh2 + kc * BATCH * 1536, 1536, 1536, 0, nt * 32, kc * 256, 16, &su.g);
            }
        }
        gsync(ls);

        // ======== phase 5: gru2 + residual + LN2 + masked h2 update
        if (bid < BATCH) {
            const int b = bid;
            const float mt_ = (t < s_dl[b]) ? 1.f : 0.f;
            float pre[2], s = 0.f, s2 = 0.f;
#pragma unroll
            for (int j = 0; j < 2; j++) {
                int i = tid + j * 256;
                int o = b * 1536 + i;
                float gir = p_gi2[o] + p_gi2[BATCH * 1536 + o] + P.g2bih[i];
                float giz = p_gi2[o + 512] + p_gi2[BATCH * 1536 + o + 512] + P.g2bih[i + 512];
                float gnn = p_gi2[o + 1024] + p_gi2[BATCH * 1536 + o + 1024] + P.g2bih[i + 1024];
                float ghr = p_gh2[o] + p_gh2[BATCH * 1536 + o] + P.g2bhh[i];
                float ghz = p_gh2[o + 512] + p_gh2[BATCH * 1536 + o + 512] + P.g2bhh[i + 512];
                float ghn = p_gh2[o + 1024] + p_gh2[BATCH * 1536 + o + 1024] + P.g2bhh[i + 1024];
                float r = sigm(gir + ghr), z = sigm(giz + ghz);
                float n = tanhf(gnn + r * ghn);
                int po = b * DECD + i;
                float ho = g_h2[po];
                float hn = (1.f - z) * n + z * ho;
                float pr = hn + g_h1res[po];
                pre[j] = pr;
                s += pr; s2 += pr * pr;
                g_h2[po] = (mt_ > 0.f) ? hn : ho;
            }
            float sum  = block_sum(s, su.a.red);
            float sum2 = block_sum(s2, su.a.red);
            float mean = sum * (1.f / 512.f);
            float var  = sum2 * (1.f / 512.f) - mean * mean;
            float inv  = rsqrtf(var + EPSV);
#pragma unroll
            for (int j = 0; j < 2; j++) {
                int i = tid + j * 256;
                g_h2res[b * DECD + i] = (pre[j] - mean) * inv * P.ln2g[i] + P.ln2b[i];
            }
        }
        gsync(ls);

        // ======== phase 6: ffn1 (64 tiles)
        for (int tl = bid; tl < 64; tl += NBLK) {
            int nt = tl >> 1, kc = tl & 1;
            gemm_tile(g_h2res, nullptr, nullptr, DECD, P.fw1, DECD, nullptr,
                      p_f1 + kc * BATCH * FFND, FFND, FFND, 0, nt * 32, kc * 256, 16, &su.g);
        }
        gsync(ls);

        // ======== phase 7: ffn2 (126 tiles), X = relu(p_f1[0]+p_f1[1]+fb1)
        for (int tl = bid; tl < 126; tl += NBLK) {
            int nt = tl >> 1, kc = tl & 1;
            gemm_tile(p_f1, p_f1 + BATCH * FFND, P.fb1, FFND, P.fw2, FFND, nullptr,
                      p_f2 + kc * BATCH * VOCAB, VOCAB, VOCAB, 0, nt * 32, kc * 512, 32, &su.g);
        }
        gsync(ls);
    }

    // ---- epilogue: pred-write for t = 158 ----
    for (int i = bid * 256 + tid; i < BATCH * VOCAB; i += NBLK * 256) {
        int b = i / VOCAB, n = i - b * VOCAB;
        float m = (158 < s_dl[b]) ? 1.f : 0.f;
        P.out[OP_OFF + ((size_t)b * TT + 158) * VOCAB + n] =
            (p_f2[b * VOCAB + n] + p_f2[BATCH * VOCAB + b * VOCAB + n] + P.fb2[n]) * m;
    }
}

// ---------------- host ----------------
extern "C" void kernel_launch(void* const* d_in, const int* in_sizes, int n_in,
                              void* d_out, int out_size) {
    (void)in_sizes; (void)n_in; (void)out_size;
    Params p;
    p.enc   = (const float*)d_in[0];
    p.caps  = (const int*)d_in[1];
    p.lens  = (const int*)d_in[2];
    p.eaw   = (const float*)d_in[3];
    p.eab   = (const float*)d_in[4];
    p.daw   = (const float*)d_in[5];
    p.dab   = (const float*)d_in[6];
    p.faw   = (const float*)d_in[7];
    p.fab   = (const float*)d_in[8];
    p.gw1   = (const float*)d_in[9];
    p.gb1   = (const float*)d_in[10];
    p.gw2   = (const float*)d_in[11];
    p.gb2   = (const float*)d_in[12];
    p.emb   = (const float*)d_in[13];
    p.g1wih = (const float*)d_in[14];
    p.g1whh = (const float*)d_in[15];
    p.g1bih = (const float*)d_in[16];
    p.g1bhh = (const float*)d_in[17];
    p.g2wih = (const float*)d_in[18];
    p.g2whh = (const float*)d_in[19];
    p.g2bih = (const float*)d_in[20];
    p.g2bhh = (const float*)d_in[21];
    p.pw    = (const float*)d_in[22];
    p.pb    = (const float*)d_in[23];
    p.ln1g  = (const float*)d_in[24];
    p.ln1b  = (const float*)d_in[25];
    p.ln2g  = (const float*)d_in[26];
    p.ln2b  = (const float*)d_in[27];
    p.fw1   = (const float*)d_in[28];
    p.fb1   = (const float*)d_in[29];
    p.fw2   = (const float*)d_in[30];
    p.fb2   = (const float*)d_in[31];
    p.out   = (float*)d_out;

    decoder_persist<<<NBLK, 256>>>(p);
}

// round 9
// speedup vs baseline: 2.0399x; 2.0399x over previous
#include <cuda_runtime.h>
#include <cstdint>
#include <cstddef>

#define NBLK  148
#define NTHR  512
#define NVH   296
#define BATCH 64
#define PP    196
#define ENCD  512
#define DECD  512
#define EMBD  256
#define ATTD  128
#define FFND  1024
#define VOCAB 2000
#define TT    159
#define MAXL  160
#define GIND  768
#define EPSV  1e-5f
#define NROW  12544   // BATCH*PP

// output: float32 concat of (preds[B,T,V], caps[B,160], dec_lens[B], alphas[B,T,P], order[B])
#define OP_OFF 0ull
#define OC_OFF 20352000ull
#define OL_OFF 20362240ull
#define OA_OFF 20362304ull
#define OO_OFF 22356800ull

// ---------------- device scratch ----------------
__device__ float g_att1t[ATTD * NROW];          // transposed att1
__device__ float g_h1[BATCH * DECD];
__device__ float g_h2[BATCH * DECD];
__device__ float g_h1res[BATCH * DECD];
__device__ float g_h2res[BATCH * DECD];
__device__ float g_gin[BATCH * GIND];
__device__ float p_gi1[6 * BATCH * 1536];
__device__ float p_proj[6 * BATCH * 512];
__device__ float p_gh1[4 * BATCH * 1536];
__device__ float p_gi2[4 * BATCH * 1536];
__device__ float p_gh2[4 * BATCH * 1536];
__device__ float p_f1[4 * BATCH * FFND];
__device__ float p_f2[4 * BATCH * VOCAB];
__device__ float p_att2[4 * BATCH * ATTD];
__device__ float p_gg[4 * BATCH * ATTD];
__device__ unsigned g_bcnt;
__device__ volatile unsigned g_bsense;

struct Params {
    const float* enc;  const int* caps;  const int* lens;
    const float *eaw, *eab, *daw, *dab, *faw, *fab;
    const float *gw1, *gb1, *gw2, *gb2, *emb;
    const float *g1wih, *g1whh, *g1bih, *g1bhh;
    const float *g2wih, *g2whh, *g2bih, *g2bhh;
    const float *pw, *pb, *ln1g, *ln1b, *ln2g, *ln2b;
    const float *fw1, *fb1, *fw2, *fb2;
    float* out;
};

struct SmemG { float Xs[2][16][68]; float Ws[2][16][36]; };
struct SmemA { float att2s[ATTD]; float alpha[224]; float red[16]; };
union  SmemU { SmemG g[2]; SmemA a; };

#define BARH(id) asm volatile("bar.sync %0, %1;" :: "r"(id), "r"(256) : "memory")

// ---------------- grid barrier ----------------
__device__ __forceinline__ void gsync(unsigned& ls) {
    __syncthreads();
    if (threadIdx.x == 0) {
        ls ^= 1u;
        __threadfence();
        if (atomicAdd(&g_bcnt, 1u) == NBLK - 1u) {
            g_bcnt = 0u;
            __threadfence();
            g_bsense = ls;
        } else {
            while (g_bsense != ls) __nanosleep(64);
        }
        __threadfence();
    }
    __syncthreads();
}

// ---------------- block reductions (512 threads) ----------------
__device__ __forceinline__ float bsum(float v, float* buf) {
    int lane = threadIdx.x & 31, w = threadIdx.x >> 5;
#pragma unroll
    for (int o = 16; o; o >>= 1) v += __shfl_down_sync(0xffffffffu, v, o);
    if (!lane) buf[w] = v;
    __syncthreads();
    if (threadIdx.x == 0) {
        float s = buf[0];
#pragma unroll
        for (int i = 1; i < 16; i++) s += buf[i];
        buf[0] = s;
    }
    __syncthreads();
    float r = buf[0];
    __syncthreads();
    return r;
}

__device__ __forceinline__ float bmax(float v, float* buf) {
    int lane = threadIdx.x & 31, w = threadIdx.x >> 5;
#pragma unroll
    for (int o = 16; o; o >>= 1) v = fmaxf(v, __shfl_down_sync(0xffffffffu, v, o));
    if (!lane) buf[w] = v;
    __syncthreads();
    if (threadIdx.x == 0) {
        float s = buf[0];
#pragma unroll
        for (int i = 1; i < 16; i++) s = fmaxf(s, buf[i]);
        buf[0] = s;
    }
    __syncthreads();
    float r = buf[0];
    __syncthreads();
    return r;
}

__device__ __forceinline__ float sigm(float x) { return 1.f / (1.f + expf(-x)); }

// ---------------- 256-thread half-block GEMM tile ----------------
// C[64 x 32] = X[64 x k-slice] @ W[N x K]^T (+bias). nparts>1: X = relu(sum parts + xb).
__device__ void gemm_tile(const float* __restrict__ X, int pstride, int nparts,
                          const float* __restrict__ xb, int ldX,
                          const float* __restrict__ W, int ldW,
                          const float* __restrict__ bias,
                          float* __restrict__ C, int ldC, int N, int transC,
                          int mbase, int nbase, int k0, int nk,
                          SmemG* sg, int barid, int ltid) {
    const int lm  = ltid >> 2;
    const int lk4 = (ltid & 3) << 2;
    const int ln  = ltid >> 3;
    const int lk2 = (ltid & 7) << 1;
    const int tx  = (ltid & 15) << 2;
    const int ty  = (ltid >> 4) << 1;

    const float* Xp = X + (size_t)(mbase + lm) * ldX + k0 + lk4;
    const int gnw = nbase + ln;
    const bool wok = gnw < N;
    const float* Wp = W + (size_t)(wok ? gnw : 0) * ldW + k0 + lk2;
    const float* xbp = xb ? xb + k0 + lk4 : nullptr;

    auto ldX4 = [&](int kt) -> float4 {
        float4 v = *(const float4*)(Xp + kt * 16);
        if (nparts > 1) {
            for (int c = 1; c < nparts; c++) {
                float4 u = *(const float4*)(Xp + (size_t)c * pstride + kt * 16);
                v.x += u.x; v.y += u.y; v.z += u.z; v.w += u.w;
            }
            const float* bb = xbp + kt * 16;
            v.x = fmaxf(v.x + bb[0], 0.f);
            v.y = fmaxf(v.y + bb[1], 0.f);
            v.z = fmaxf(v.z + bb[2], 0.f);
            v.w = fmaxf(v.w + bb[3], 0.f);
        }
        return v;
    };

    float4 xr = ldX4(0);
    float2 wr = wok ? *(const float2*)Wp : make_float2(0.f, 0.f);

    BARH(barid);               // protect smem vs previous tile on this half
    sg->Xs[0][lk4 + 0][lm] = xr.x;
    sg->Xs[0][lk4 + 1][lm] = xr.y;
    sg->Xs[0][lk4 + 2][lm] = xr.z;
    sg->Xs[0][lk4 + 3][lm] = xr.w;
    sg->Ws[0][lk2 + 0][ln] = wr.x;
    sg->Ws[0][lk2 + 1][ln] = wr.y;

    float acc[4][2] = {};
    int buf = 0;
    for (int kt = 0; kt < nk; kt++) {
        if (kt + 1 < nk) {
            xr = ldX4(kt + 1);
            wr = wok ? *(const float2*)(Wp + (kt + 1) * 16) : make_float2(0.f, 0.f);
        }
        BARH(barid);
#pragma unroll
        for (int kk = 0; kk < 16; kk++) {
            const float4 a = *(const float4*)&sg->Xs[buf][kk][tx];
            const float2 b = *(const float2*)&sg->Ws[buf][kk][ty];
            acc[0][0] = fmaf(a.x, b.x, acc[0][0]); acc[0][1] = fmaf(a.x, b.y, acc[0][1]);
            acc[1][0] = fmaf(a.y, b.x, acc[1][0]); acc[1][1] = fmaf(a.y, b.y, acc[1][1]);
            acc[2][0] = fmaf(a.z, b.x, acc[2][0]); acc[2][1] = fmaf(a.z, b.y, acc[2][1]);
            acc[3][0] = fmaf(a.w, b.x, acc[3][0]); acc[3][1] = fmaf(a.w, b.y, acc[3][1]);
        }
        if (kt + 1 < nk) {
            int nb = buf ^ 1;
            sg->Xs[nb][lk4 + 0][lm] = xr.x;
            sg->Xs[nb][lk4 + 1][lm] = xr.y;
            sg->Xs[nb][lk4 + 2][lm] = xr.z;
            sg->Xs[nb][lk4 + 3][lm] = xr.w;
            sg->Ws[nb][lk2 + 0][ln] = wr.x;
            sg->Ws[nb][lk2 + 1][ln] = wr.y;
            buf = nb;
        }
    }
#pragma unroll
    for (int i = 0; i < 4; i++) {
        int gm = mbase + tx + i;
#pragma unroll
        for (int j = 0; j < 2; j++) {
            int gn = nbase + ty + j;
            if (gn < N) {
                float v = acc[i][j] + (bias ? bias[gn] : 0.f);
                if (transC) C[(size_t)gn * ldC + gm] = v;
                else        C[(size_t)gm * ldC + gn] = v;
            }
        }
    }
}

// ---------------- persistent kernel ----------------
__global__ void __launch_bounds__(NTHR, 1) decoder_persist(Params P) {
    __shared__ SmemU su;
    __shared__ int s_ord[BATCH];
    __shared__ int s_dl[BATCH];

    const int tid  = threadIdx.x;
    const int bid  = blockIdx.x;
    const int half = tid >> 8;
    const int ltid = tid & 255;
    const int barid = 1 + half;
    const int vid0 = half * NBLK + bid;
    unsigned ls = g_bsense;

    // stable descending argsort (rank-based; ties keep original order)
    if (tid < BATCH) {
        int Li = P.lens[tid];
        int r = 0;
        for (int j = 0; j < BATCH; j++) {
            int Lj = P.lens[j];
            r += (Lj > Li) || (Lj == Li && j < tid);
        }
        s_ord[r] = tid;
        s_dl[r]  = Li - 1;
    }
    __syncthreads();

    // prologue: static outputs + state init
    if (bid == 0) {
        if (tid < BATCH) {
            P.out[OL_OFF + tid] = (float)s_dl[tid];
            P.out[OO_OFF + tid] = (float)s_ord[tid];
        }
        for (int i = tid; i < BATCH * MAXL; i += NTHR)
            P.out[OC_OFF + i] = (float)P.caps[s_ord[i / MAXL] * MAXL + (i % MAXL)];
    }
    if (bid < BATCH) {
        g_h1[bid * DECD + tid] = 0.f;
        g_h2[bid * DECD + tid] = 0.f;
    }
    for (int i = bid * NTHR + tid; i < 4 * BATCH * ATTD; i += NBLK * NTHR) {
        p_att2[i] = 0.f;   // h0 = 0 -> step-0 att2/gg GEMM results are 0
        p_gg[i]   = 0.f;
    }

    // att1T[a][row] = (enc @ eaw^T + eab) transposed, original batch order
    for (int v = vid0; v < PP * 4; v += NVH) {
        int mt = v >> 2, nt = v & 3;
        gemm_tile(P.enc, 0, 1, nullptr, ENCD, P.eaw, ENCD, P.eab,
                  g_att1t, NROW, ATTD, 1, mt * 64, nt * 32, 0, 32, &su.g[half], barid, ltid);
    }
    gsync(ls);

    for (int t = 0; t < TT; t++) {
        // ===== P1: attention (blocks 0..63, full block) | gh1 GEMM (blocks 64..147 halves)
        if (bid < BATCH) {
            const int b = bid, ob = s_ord[b];
            SmemA* A = &su.a;
            float gv = 0.f;
            if (tid < ATTD) {
                int o = b * ATTD + tid;
                float a2 = p_att2[o] + p_att2[BATCH * ATTD + o]
                         + p_att2[2 * BATCH * ATTD + o] + p_att2[3 * BATCH * ATTD + o]
                         + P.dab[tid];
                A->att2s[tid] = a2;
                float gg = fmaxf(p_gg[o] + p_gg[BATCH * ATTD + o]
                               + p_gg[2 * BATCH * ATTD + o] + p_gg[3 * BATCH * ATTD + o]
                               + P.gb1[tid], 0.f);
                gv = gg * P.gw2[tid];
            }
            float gate = sigm(bsum(gv, A->red) + P.gb2[0]);

            float e = -1e30f;
            if (tid < PP) {
                const float* at = g_att1t + (size_t)ob * PP + tid;
                float s = 0.f;
#pragma unroll 8
                for (int a = 0; a < ATTD; a++)
                    s += P.faw[a] * fmaxf(at[(size_t)a * NROW] + A->att2s[a], 0.f);
                e = s + P.fab[0];
            }
            float mx  = bmax(e, A->red);
            float ev  = (tid < PP) ? expf(e - mx) : 0.f;
            float inv = 1.f / bsum(ev, A->red);
            float mt_ = (t < s_dl[b]) ? 1.f : 0.f;
            if (tid < PP) {
                float al = ev * inv;
                A->alpha[tid] = al;
                P.out[OA_OFF + ((size_t)b * TT + t) * PP + tid] = al * mt_;
            }
            __syncthreads();

            float aw = 0.f;
            const float* eb = P.enc + (size_t)ob * PP * ENCD + tid;
#pragma unroll 4
            for (int p = 0; p < PP; p++) aw += A->alpha[p] * eb[(size_t)p * ENCD];
            g_gin[b * GIND + EMBD + tid] = aw * gate;
            if (tid < EMBD) {
                int cap = P.caps[ob * MAXL + t];
                g_gin[b * GIND + tid] = P.emb[(size_t)cap * EMBD + tid];
            }
        } else {
            int w = (half == 0) ? (bid - BATCH) : (84 + bid - BATCH);   // 0..167
            for (int u = w; u < 192; u += 168) {
                int nt = u >> 2, kc = u & 3;
                gemm_tile(g_h1, 0, 1, nullptr, DECD, P.g1whh, DECD, nullptr,
                          p_gh1 + kc * BATCH * 1536, 1536, 1536, 0,
                          0, nt * 32, kc * 128, 8, &su.g[half], barid, ltid);
            }
        }
        gsync(ls);

        // ===== P2: gi1 (288) + proj (96) + pred-write t-1 (64 workers)
        for (int v = vid0; v < 448; v += NVH) {
            if (v < 288) {
                int nt = v / 6, kc = v % 6;
                gemm_tile(g_gin, 0, 1, nullptr, GIND, P.g1wih, GIND, nullptr,
                          p_gi1 + kc * BATCH * 1536, 1536, 1536, 0,
                          0, nt * 32, kc * 128, 8, &su.g[half], barid, ltid);
            } else if (v < 384) {
                int u = v - 288, nt = u / 6, kc = u % 6;
                gemm_tile(g_gin, 0, 1, nullptr, GIND, P.pw, GIND, nullptr,
                          p_proj + kc * BATCH * 512, 512, 512, 0,
                          0, nt * 32, kc * 128, 8, &su.g[half], barid, ltid);
            } else if (t > 0) {
                int pw_ = v - 384;                  // 0..63
                for (int i = pw_ * 256 + ltid; i < BATCH * VOCAB; i += 64 * 256) {
                    int b = i / VOCAB, n = i - b * VOCAB;
                    float m = ((t - 1) < s_dl[b]) ? 1.f : 0.f;
                    float val = p_f2[i] + p_f2[BATCH * VOCAB + i]
                              + p_f2[2 * BATCH * VOCAB + i] + p_f2[3 * BATCH * VOCAB + i]
                              + P.fb2[n];
                    P.out[OP_OFF + ((size_t)b * TT + (t - 1)) * VOCAB + n] = val * m;
                }
            }
        }
        gsync(ls);

        // ===== P3: gru1+LN1 (blocks 0..63) | gh2 GEMM (blocks 64..147)
        if (bid < BATCH) {
            const int b = bid, i = tid;
            const float mt_ = (t < s_dl[b]) ? 1.f : 0.f;
            float gir = P.g1bih[i], giz = P.g1bih[512 + i], gnn = P.g1bih[1024 + i];
#pragma unroll
            for (int c = 0; c < 6; c++) {
                int o = c * BATCH * 1536 + b * 1536;
                gir += p_gi1[o + i];
                giz += p_gi1[o + 512 + i];
                gnn += p_gi1[o + 1024 + i];
            }
            float ghr = P.g1bhh[i], ghz = P.g1bhh[512 + i], ghn = P.g1bhh[1024 + i];
#pragma unroll
            for (int c = 0; c < 4; c++) {
                int o = c * BATCH * 1536 + b * 1536;
                ghr += p_gh1[o + i];
                ghz += p_gh1[o + 512 + i];
                ghn += p_gh1[o + 1024 + i];
            }
            float pj = P.pb[i];
#pragma unroll
            for (int c = 0; c < 6; c++) pj += p_proj[c * BATCH * 512 + b * 512 + i];
            float r = sigm(gir + ghr), z = sigm(giz + ghz);
            float n = tanhf(gnn + r * ghn);
            float ho = g_h1[b * DECD + i];
            float hn = (1.f - z) * n + z * ho;
            float pr = hn + pj;
            float sum  = bsum(pr, su.a.red);
            float sum2 = bsum(pr * pr, su.a.red);
            float mean = sum * (1.f / 512.f);
            float var  = sum2 * (1.f / 512.f) - mean * mean;
            float inv  = rsqrtf(var + EPSV);
            g_h1[b * DECD + i] = (mt_ > 0.f) ? hn : ho;
            g_h1res[b * DECD + i] = (pr - mean) * inv * P.ln1g[i] + P.ln1b[i];
        } else {
            int w = (half == 0) ? (bid - BATCH) : (84 + bid - BATCH);
            for (int u = w; u < 192; u += 168) {
                int nt = u >> 2, kc = u & 3;
                gemm_tile(g_h2, 0, 1, nullptr, DECD, P.g2whh, DECD, nullptr,
                          p_gh2 + kc * BATCH * 1536, 1536, 1536, 0,
                          0, nt * 32, kc * 128, 8, &su.g[half], barid, ltid);
            }
        }
        gsync(ls);

        // ===== P4: gi2 (192 tiles)
        for (int v = vid0; v < 192; v += NVH) {
            int nt = v >> 2, kc = v & 3;
            gemm_tile(g_h1res, 0, 1, nullptr, DECD, P.g2wih, DECD, nullptr,
                      p_gi2 + kc * BATCH * 1536, 1536, 1536, 0,
                      0, nt * 32, kc * 128, 8, &su.g[half], barid, ltid);
        }
        gsync(ls);

        // ===== P5: gru2 + residual + LN2
        if (bid < BATCH) {
            const int b = bid, i = tid;
            const float mt_ = (t < s_dl[b]) ? 1.f : 0.f;
            float gir = P.g2bih[i], giz = P.g2bih[512 + i], gnn = P.g2bih[1024 + i];
#pragma unroll
            for (int c = 0; c < 4; c++) {
                int o = c * BATCH * 1536 + b * 1536;
                gir += p_gi2[o + i];
                giz += p_gi2[o + 512 + i];
                gnn += p_gi2[o + 1024 + i];
            }
            float ghr = P.g2bhh[i], ghz = P.g2bhh[512 + i], ghn = P.g2bhh[1024 + i];
#pragma unroll
            for (int c = 0; c < 4; c++) {
                int o = c * BATCH * 1536 + b * 1536;
                ghr += p_gh2[o + i];
                ghz += p_gh2[o + 512 + i];
                ghn += p_gh2[o + 1024 + i];
            }
            float r = sigm(gir + ghr), z = sigm(giz + ghz);
            float n = tanhf(gnn + r * ghn);
            float ho = g_h2[b * DECD + i];
            float hn = (1.f - z) * n + z * ho;
            float pr = hn + g_h1res[b * DECD + i];
            float sum  = bsum(pr, su.a.red);
            float sum2 = bsum(pr * pr, su.a.red);
            float mean = sum * (1.f / 512.f);
            float var  = sum2 * (1.f / 512.f) - mean * mean;
            float inv  = rsqrtf(var + EPSV);
            g_h2[b * DECD + i] = (mt_ > 0.f) ? hn : ho;
            g_h2res[b * DECD + i] = (pr - mean) * inv * P.ln2g[i] + P.ln2b[i];
        }
        gsync(ls);

        // ===== P6: ffn1 (128 tiles)
        for (int v = vid0; v < 128; v += NVH) {
            int nt = v >> 2, kc = v & 3;
            gemm_tile(g_h2res, 0, 1, nullptr, DECD, P.fw1, DECD, nullptr,
                      p_f1 + kc * BATCH * FFND, FFND, FFND, 0,
                      0, nt * 32, kc * 128, 8, &su.g[half], barid, ltid);
        }
        gsync(ls);

        // ===== P7: ffn2 (252) + att2-next (16) + gg-next (16)
        for (int v = vid0; v < 284; v += NVH) {
            if (v < 252) {
                int nt = v >> 2, kc = v & 3;
                gemm_tile(p_f1, BATCH * FFND, 4, P.fb1, FFND, P.fw2, FFND, nullptr,
                          p_f2 + kc * BATCH * VOCAB, VOCAB, VOCAB, 0,
                          0, nt * 32, kc * 256, 16, &su.g[half], barid, ltid);
            } else if (v < 268) {
                int u = v - 252, nt = u >> 2, kc = u & 3;
                gemm_tile(g_h2, 0, 1, nullptr, DECD, P.daw, DECD, nullptr,
                          p_att2 + kc * BATCH * ATTD, ATTD, ATTD, 0,
                          0, nt * 32, kc * 128, 8, &su.g[half], barid, ltid);
            } else {
                int u = v - 268, nt = u >> 2, kc = u & 3;
                gemm_tile(g_h2, 0, 1, nullptr, DECD, P.gw1, DECD, nullptr,
                          p_gg + kc * BATCH * ATTD, ATTD, ATTD, 0,
                          0, nt * 32, kc * 128, 8, &su.g[half], barid, ltid);
            }
        }
        gsync(ls);
    }

    // epilogue: pred-write for t = 158
    for (int i = bid * NTHR + tid; i < BATCH * VOCAB; i += NBLK * NTHR) {
        int b = i / VOCAB, n = i - b * VOCAB;
        float m = (158 < s_dl[b]) ? 1.f : 0.f;
        float val = p_f2[i] + p_f2[BATCH * VOCAB + i]
                  + p_f2[2 * BATCH * VOCAB + i] + p_f2[3 * BATCH * VOCAB + i]
                  + P.fb2[n];
        P.out[OP_OFF + ((size_t)b * TT + 158) * VOCAB + n] = val * m;
    }
}

// ---------------- host ----------------
extern "C" void kernel_launch(void* const* d_in, const int* in_sizes, int n_in,
                              void* d_out, int out_size) {
    (void)in_sizes; (void)n_in; (void)out_size;
    Params p;
    p.enc   = (const float*)d_in[0];
    p.caps  = (const int*)d_in[1];
    p.lens  = (const int*)d_in[2];
    p.eaw   = (const float*)d_in[3];
    p.eab   = (const float*)d_in[4];
    p.daw   = (const float*)d_in[5];
    p.dab   = (const float*)d_in[6];
    p.faw   = (const float*)d_in[7];
    p.fab   = (const float*)d_in[8];
    p.gw1   = (const float*)d_in[9];
    p.gb1   = (const float*)d_in[10];
    p.gw2   = (const float*)d_in[11];
    p.gb2   = (const float*)d_in[12];
    p.emb   = (const float*)d_in[13];
    p.g1wih = (const float*)d_in[14];
    p.g1whh = (const float*)d_in[15];
    p.g1bih = (const float*)d_in[16];
    p.g1bhh = (const float*)d_in[17];
    p.g2wih = (const float*)d_in[18];
    p.g2whh = (const float*)d_in[19];
    p.g2bih = (const float*)d_in[20];
    p.g2bhh = (const float*)d_in[21];
    p.pw    = (const float*)d_in[22];
    p.pb    = (const float*)d_in[23];
    p.ln1g  = (const float*)d_in[24];
    p.ln1b  = (const float*)d_in[25];
    p.ln2g  = (const float*)d_in[26];
    p.ln2b  = (const float*)d_in[27];
    p.fw1   = (const float*)d_in[28];
    p.fb1   = (const float*)d_in[29];
    p.fw2   = (const float*)d_in[30];
    p.fb2   = (const float*)d_in[31];
    p.out   = (float*)d_out;

    decoder_persist<<<NBLK, NTHR>>>(p);
}

// round 11
// speedup vs baseline: 2.1723x; 1.0649x over previous
#include <cuda_runtime.h>
#include <cstdint>
#include <cstddef>

#define NBLK  148
#define NTHR  512
#define BATCH 64
#define PP    196
#define ENCD  512
#define DECD  512
#define EMBD  256
#define ATTD  128
#define FFND  1024
#define VOCAB 2000
#define TT    159
#define MAXL  160
#define GIND  768
#define EPSV  1e-5f
#define NROW  12544

// output: float32 concat of (preds[B,T,V], caps[B,160], dec_lens[B], alphas[B,T,P], order[B])
#define OP_OFF 0ull
#define OC_OFF 20352000ull
#define OL_OFF 20362240ull
#define OA_OFF 20362304ull
#define OO_OFF 22356800ull

// ---------------- device scratch ----------------
__device__ float g_att1t[ATTD * NROW];
__device__ float g_h1[BATCH * DECD];
__device__ float g_h2[BATCH * DECD];
__device__ float g_h1res[BATCH * DECD];
__device__ float g_h2res[BATCH * DECD];
__device__ float g_gin[BATCH * GIND];
__device__ float p_gi1[6 * BATCH * 1536];
__device__ float p_proj[6 * BATCH * 512];
__device__ float p_gh1[4 * BATCH * 1536];
__device__ float p_gh2[4 * BATCH * 1536];
__device__ float p_gi2[4 * BATCH * 1536];
__device__ float p_f1[4 * BATCH * FFND];
__device__ float p_f2[8 * BATCH * VOCAB];
__device__ float p_att2[4 * BATCH * ATTD];
__device__ float p_gg[4 * BATCH * ATTD];
__device__ unsigned g_bcnt;
__device__ volatile unsigned g_bsense;

struct Params {
    const float* enc;  const int* caps;  const int* lens;
    const float *eaw, *eab, *daw, *dab, *faw, *fab;
    const float *gw1, *gb1, *gw2, *gb2, *emb;
    const float *g1wih, *g1whh, *g1bih, *g1bhh;
    const float *g2wih, *g2whh, *g2bih, *g2bhh;
    const float *pw, *pb, *ln1g, *ln1b, *ln2g, *ln2b;
    const float *fw1, *fb1, *fw2, *fb2;
    float* out;
};

struct SmemG { float Xs[2][16][68]; float Ws[2][16][132]; };
struct SmemA { float att2s[ATTD]; float alpha[224]; float red[16]; };

#define BARH(id) asm volatile("bar.sync %0, %1;" :: "r"(id), "r"(256) : "memory")

typedef unsigned long long u64;

__device__ __forceinline__ void ffma2(u64& d, u64 a, u64 b) {
    asm("fma.rn.f32x2 %0, %1, %2, %0;" : "+l"(d) : "l"(a), "l"(b));
}
__device__ __forceinline__ u64 dup2(float x) {
    u64 r; unsigned xi = __float_as_uint(x);
    asm("mov.b64 %0, {%1, %1};" : "=l"(r) : "r"(xi));
    return r;
}
__device__ __forceinline__ void unpk(u64 v, float& lo, float& hi) {
    unsigned a, b;
    asm("mov.b64 {%0, %1}, %2;" : "=r"(a), "=r"(b) : "l"(v));
    lo = __uint_as_float(a); hi = __uint_as_float(b);
}

// ---------------- grid barrier ----------------
__device__ __forceinline__ void gsync(unsigned& ls) {
    __syncthreads();
    if (threadIdx.x == 0) {
        ls ^= 1u;
        __threadfence();
        if (atomicAdd(&g_bcnt, 1u) == NBLK - 1u) {
            g_bcnt = 0u;
            __threadfence();
            g_bsense = ls;
        } else {
            while (g_bsense != ls) __nanosleep(32);
        }
        __threadfence();
    }
    __syncthreads();
}

// ---------------- block reductions (512 threads) ----------------
__device__ __forceinline__ float bsum(float v, float* buf) {
    int lane = threadIdx.x & 31, w = threadIdx.x >> 5;
#pragma unroll
    for (int o = 16; o; o >>= 1) v += __shfl_down_sync(0xffffffffu, v, o);
    if (!lane) buf[w] = v;
    __syncthreads();
    if (threadIdx.x == 0) {
        float s = buf[0];
#pragma unroll
        for (int i = 1; i < 16; i++) s += buf[i];
        buf[0] = s;
    }
    __syncthreads();
    float r = buf[0];
    __syncthreads();
    return r;
}
__device__ __forceinline__ float bmax(float v, float* buf) {
    int lane = threadIdx.x & 31, w = threadIdx.x >> 5;
#pragma unroll
    for (int o = 16; o; o >>= 1) v = fmaxf(v, __shfl_down_sync(0xffffffffu, v, o));
    if (!lane) buf[w] = v;
    __syncthreads();
    if (threadIdx.x == 0) {
        float s = buf[0];
#pragma unroll
        for (int i = 1; i < 16; i++) s = fmaxf(s, buf[i]);
        buf[0] = s;
    }
    __syncthreads();
    float r = buf[0];
    __syncthreads();
    return r;
}
__device__ __forceinline__ float sigm(float x) { return 1.f / (1.f + expf(-x)); }

// ---------------- half-block GEMM tile: C[64 x 128] = X @ W^T ----------------
// 256 threads, microtile 4x8, f32x2 packed FMA, double-buffered BK=16.
// nparts>1: X element = relu(sum of nparts partials + xb[k]).
__device__ void gemm_tile(const float* __restrict__ X, int pstride, int nparts,
                          const float* __restrict__ xb, int ldX,
                          const float* __restrict__ W, int ldW,
                          const float* __restrict__ bias,
                          float* __restrict__ C, int ldC, int N, int transC,
                          int mbase, int nbase, int k0, int nk,
                          SmemG* sg, int barid, int ltid) {
    const int lr  = ltid >> 2;            // 0..63
    const int lk4 = (ltid & 3) << 2;      // 0,4,8,12
    const int tx  = (ltid & 15) << 2;     // row group
    const int ty  = (ltid >> 4) << 3;     // col group (8 wide)

    const float* Xp = X + (size_t)(mbase + lr) * ldX + k0 + lk4;
    const int wn0 = nbase + lr, wn1 = wn0 + 64;
    const bool w0ok = wn0 < N, w1ok = wn1 < N;
    const float* Wp0 = W + (size_t)(w0ok ? wn0 : 0) * ldW + k0 + lk4;
    const float* Wp1 = W + (size_t)(w1ok ? wn1 : 0) * ldW + k0 + lk4;
    const float* xbp = xb ? xb + k0 + lk4 : nullptr;

    auto ldX4 = [&](int kt) -> float4 {
        float4 v = *(const float4*)(Xp + kt * 16);
        if (nparts > 1) {
#pragma unroll
            for (int c = 1; c < 4; c++) {
                if (c >= nparts) break;
                float4 u = *(const float4*)(Xp + (size_t)c * pstride + kt * 16);
                v.x += u.x; v.y += u.y; v.z += u.z; v.w += u.w;
            }
            const float* bb = xbp + kt * 16;
            v.x = fmaxf(v.x + bb[0], 0.f);
            v.y = fmaxf(v.y + bb[1], 0.f);
            v.z = fmaxf(v.z + bb[2], 0.f);
            v.w = fmaxf(v.w + bb[3], 0.f);
        }
        return v;
    };

    float4 xr = ldX4(0);
    float4 wr0 = w0ok ? *(const float4*)Wp0 : make_float4(0.f,0.f,0.f,0.f);
    float4 wr1 = w1ok ? *(const float4*)Wp1 : make_float4(0.f,0.f,0.f,0.f);

    BARH(barid);
    sg->Xs[0][lk4+0][lr] = xr.x; sg->Xs[0][lk4+1][lr] = xr.y;
    sg->Xs[0][lk4+2][lr] = xr.z; sg->Xs[0][lk4+3][lr] = xr.w;
    sg->Ws[0][lk4+0][lr] = wr0.x; sg->Ws[0][lk4+1][lr] = wr0.y;
    sg->Ws[0][lk4+2][lr] = wr0.z; sg->Ws[0][lk4+3][lr] = wr0.w;
    sg->Ws[0][lk4+0][lr+64] = wr1.x; sg->Ws[0][lk4+1][lr+64] = wr1.y;
    sg->Ws[0][lk4+2][lr+64] = wr1.z; sg->Ws[0][lk4+3][lr+64] = wr1.w;

    u64 acc[4][4] = {};
    int buf = 0;
    for (int kt = 0; kt < nk; kt++) {
        if (kt + 1 < nk) {
            xr  = ldX4(kt + 1);
            wr0 = w0ok ? *(const float4*)(Wp0 + (kt+1)*16) : make_float4(0.f,0.f,0.f,0.f);
            wr1 = w1ok ? *(const float4*)(Wp1 + (kt+1)*16) : make_float4(0.f,0.f,0.f,0.f);
        }
        BARH(barid);
#pragma unroll
        for (int kk = 0; kk < 16; kk++) {
            const float4 a = *(const float4*)&sg->Xs[buf][kk][tx];
            const float* wrow = &sg->Ws[buf][kk][ty];
            u64 b0 = *(const u64*)(wrow + 0);
            u64 b1 = *(const u64*)(wrow + 2);
            u64 b2 = *(const u64*)(wrow + 4);
            u64 b3 = *(const u64*)(wrow + 6);
            u64 pa;
            pa = dup2(a.x);
            ffma2(acc[0][0], pa, b0); ffma2(acc[0][1], pa, b1);
            ffma2(acc[0][2], pa, b2); ffma2(acc[0][3], pa, b3);
            pa = dup2(a.y);
            ffma2(acc[1][0], pa, b0); ffma2(acc[1][1], pa, b1);
            ffma2(acc[1][2], pa, b2); ffma2(acc[1][3], pa, b3);
            pa = dup2(a.z);
            ffma2(acc[2][0], pa, b0); ffma2(acc[2][1], pa, b1);
            ffma2(acc[2][2], pa, b2); ffma2(acc[2][3], pa, b3);
            pa = dup2(a.w);
            ffma2(acc[3][0], pa, b0); ffma2(acc[3][1], pa, b1);
            ffma2(acc[3][2], pa, b2); ffma2(acc[3][3], pa, b3);
        }
        if (kt + 1 < nk) {
            int nb = buf ^ 1;
            sg->Xs[nb][lk4+0][lr] = xr.x; sg->Xs[nb][lk4+1][lr] = xr.y;
            sg->Xs[nb][lk4+2][lr] = xr.z; sg->Xs[nb][lk4+3][lr] = xr.w;
            sg->Ws[nb][lk4+0][lr] = wr0.x; sg->Ws[nb][lk4+1][lr] = wr0.y;
            sg->Ws[nb][lk4+2][lr] = wr0.z; sg->Ws[nb][lk4+3][lr] = wr0.w;
            sg->Ws[nb][lk4+0][lr+64] = wr1.x; sg->Ws[nb][lk4+1][lr+64] = wr1.y;
            sg->Ws[nb][lk4+2][lr+64] = wr1.z; sg->Ws[nb][lk4+3][lr+64] = wr1.w;
            buf = nb;
        }
    }
#pragma unroll
    for (int i = 0; i < 4; i++) {
        int gm = mbase + tx + i;
#pragma unroll
        for (int jp = 0; jp < 4; jp++) {
            float lo, hi;
            unpk(acc[i][jp], lo, hi);
            int gn = nbase + ty + 2*jp;
            if (gn < N) {
                float v = lo + (bias ? bias[gn] : 0.f);
                if (transC) C[(size_t)gn * ldC + gm] = v; else C[(size_t)gm * ldC + gn] = v;
            }
            if (gn + 1 < N) {
                float v = hi + (bias ? bias[gn+1] : 0.f);
                if (transC) C[(size_t)(gn+1) * ldC + gm] = v; else C[(size_t)gm * ldC + gn + 1] = v;
            }
        }
    }
}

// ---------------- persistent kernel ----------------
__global__ void __launch_bounds__(NTHR, 1) decoder_persist(Params P) {
    extern __shared__ char dsm[];
    SmemG* G = reinterpret_cast<SmemG*>(dsm);                        // [2]
    SmemA* A = reinterpret_cast<SmemA*>(dsm + 2 * sizeof(SmemG));
    __shared__ int s_ord[BATCH];
    __shared__ int s_dl[BATCH];

    const int tid  = threadIdx.x;
    const int bid  = blockIdx.x;
    const int half = tid >> 8;
    const int ltid = tid & 255;
    const int barid = 1 + half;
    const int vid0 = half * NBLK + bid;      // 0..295
    unsigned ls = g_bsense;

    if (tid < BATCH) {
        int Li = P.lens[tid];
        int r = 0;
        for (int j = 0; j < BATCH; j++) {
            int Lj = P.lens[j];
            r += (Lj > Li) || (Lj == Li && j < tid);
        }
        s_ord[r] = tid;
        s_dl[r]  = Li - 1;
    }
    __syncthreads();

    if (bid == 0) {
        if (tid < BATCH) {
            P.out[OL_OFF + tid] = (float)s_dl[tid];
            P.out[OO_OFF + tid] = (float)s_ord[tid];
        }
        for (int i = tid; i < BATCH * MAXL; i += NTHR)
            P.out[OC_OFF + i] = (float)P.caps[s_ord[i / MAXL] * MAXL + (i % MAXL)];
    }
    if (bid < BATCH) {
        g_h1[bid * DECD + tid] = 0.f;
        g_h2[bid * DECD + tid] = 0.f;
    }
    for (int i = bid * NTHR + tid; i < 4 * BATCH * ATTD; i += NBLK * NTHR) {
        p_att2[i] = 0.f;
        p_gg[i]   = 0.f;
    }

    // prologue: att1T (transposed), 196 m-tiles, N=128, K=512
    for (int v = vid0; v < 196; v += 296)
        gemm_tile(P.enc, 0, 1, nullptr, ENCD, P.eaw, ENCD, P.eab,
                  g_att1t, NROW, ATTD, 1, v * 64, 0, 0, 32, &G[half], barid, ltid);
    gsync(ls);

    for (int t = 0; t < TT; t++) {
        // ===== P1: attention (bid<64) | gh1 (48) + gh2 (48) on other halves
        if (bid < BATCH) {
            const int b = bid, ob = s_ord[b];
            float gv = 0.f;
            if (tid < ATTD) {
                int o = b * ATTD + tid;
                float a2 = P.dab[tid], gg = P.gb1[tid];
#pragma unroll
                for (int c = 0; c < 4; c++) {
                    a2 += p_att2[c * BATCH * ATTD + o];
                    gg += p_gg[c * BATCH * ATTD + o];
                }
                A->att2s[tid] = a2;
                gv = fmaxf(gg, 0.f) * P.gw2[tid];
            }
            float gate = sigm(bsum(gv, A->red) + P.gb2[0]);

            float e = -1e30f;
            if (tid < PP) {
                const float* at = g_att1t + (size_t)ob * PP + tid;
                float s = 0.f;
#pragma unroll 8
                for (int a = 0; a < ATTD; a++)
                    s += P.faw[a] * fmaxf(at[(size_t)a * NROW] + A->att2s[a], 0.f);
                e = s + P.fab[0];
            }
            float mx  = bmax(e, A->red);
            float ev  = (tid < PP) ? expf(e - mx) : 0.f;
            float inv = 1.f / bsum(ev, A->red);
            float mt_ = (t < s_dl[b]) ? 1.f : 0.f;
            if (tid < PP) {
                float al = ev * inv;
                A->alpha[tid] = al;
                P.out[OA_OFF + ((size_t)b * TT + t) * PP + tid] = al * mt_;
            }
            __syncthreads();

            float aw0 = 0.f, aw1 = 0.f;
            const float* eb = P.enc + (size_t)ob * PP * ENCD + tid;
#pragma unroll 4
            for (int p = 0; p < PP; p += 2) {
                aw0 += A->alpha[p]     * eb[(size_t)p * ENCD];
                aw1 += A->alpha[p + 1] * eb[(size_t)(p + 1) * ENCD];
            }
            g_gin[b * GIND + EMBD + tid] = (aw0 + aw1) * gate;
            if (tid < EMBD) {
                int cap = P.caps[ob * MAXL + t];
                g_gin[b * GIND + tid] = P.emb[(size_t)cap * EMBD + tid];
            }
        } else {
            int w = half * 84 + (bid - BATCH);     // 0..167
            if (w < 48) {
                int nt = w >> 2, kc = w & 3;
                gemm_tile(g_h1, 0, 1, nullptr, DECD, P.g1whh, DECD, nullptr,
                          p_gh1 + kc * BATCH * 1536, 1536, 1536, 0,
                          0, nt * 128, kc * 128, 8, &G[half], barid, ltid);
            } else if (w < 96) {
                int u = w - 48, nt = u >> 2, kc = u & 3;
                gemm_tile(g_h2, 0, 1, nullptr, DECD, P.g2whh, DECD, nullptr,
                          p_gh2 + kc * BATCH * 1536, 1536, 1536, 0,
                          0, nt * 128, kc * 128, 8, &G[half], barid, ltid);
            }
        }
        gsync(ls);

        // ===== P2: gi1 (72) + proj (24) + pred-write t-1 (64 halves)
        {
            int v = vid0;
            if (v < 72) {
                int nt = v / 6, kc = v % 6;
                gemm_tile(g_gin, 0, 1, nullptr, GIND, P.g1wih, GIND, nullptr,
                          p_gi1 + kc * BATCH * 1536, 1536, 1536, 0,
                          0, nt * 128, kc * 128, 8, &G[half], barid, ltid);
            } else if (v < 96) {
                int u = v - 72, nt = u / 6, kc = u % 6;
                gemm_tile(g_gin, 0, 1, nullptr, GIND, P.pw, GIND, nullptr,
                          p_proj + kc * BATCH * 512, 512, 512, 0,
                          0, nt * 128, kc * 128, 8, &G[half], barid, ltid);
            } else if (v < 160 && t > 0) {
                int pw_ = v - 96;
                for (int i = pw_ * 256 + ltid; i < BATCH * VOCAB; i += 64 * 256) {
                    int b = i / VOCAB, n = i - b * VOCAB;
                    float m = ((t - 1) < s_dl[b]) ? 1.f : 0.f;
                    float val = P.fb2[n];
#pragma unroll
                    for (int c = 0; c < 8; c++) val += p_f2[c * BATCH * VOCAB + i];
                    P.out[OP_OFF + ((size_t)b * TT + (t - 1)) * VOCAB + n] = val * m;
                }
            }
        }
        gsync(ls);

        // ===== P3: gru1 + proj + LN1
        if (bid < BATCH) {
            const int b = bid, i = tid;
            const float mt_ = (t < s_dl[b]) ? 1.f : 0.f;
            float gir = P.g1bih[i], giz = P.g1bih[512 + i], gnn = P.g1bih[1024 + i];
#pragma unroll
            for (int c = 0; c < 6; c++) {
                int o = c * BATCH * 1536 + b * 1536;
                gir += p_gi1[o + i]; giz += p_gi1[o + 512 + i]; gnn += p_gi1[o + 1024 + i];
            }
            float ghr = P.g1bhh[i], ghz = P.g1bhh[512 + i], ghn = P.g1bhh[1024 + i];
#pragma unroll
            for (int c = 0; c < 4; c++) {
                int o = c * BATCH * 1536 + b * 1536;
                ghr += p_gh1[o + i]; ghz += p_gh1[o + 512 + i]; ghn += p_gh1[o + 1024 + i];
            }
            float pj = P.pb[i];
#pragma unroll
            for (int c = 0; c < 6; c++) pj += p_proj[c * BATCH * 512 + b * 512 + i];
            float r = sigm(gir + ghr), z = sigm(giz + ghz);
            float n = tanhf(gnn + r * ghn);
            float ho = g_h1[b * DECD + i];
            float hn = (1.f - z) * n + z * ho;
            float pr = hn + pj;
            float sum  = bsum(pr, A->red);
            float sum2 = bsum(pr * pr, A->red);
            float mean = sum * (1.f / 512.f);
            float var  = sum2 * (1.f / 512.f) - mean * mean;
            float inv  = rsqrtf(var + EPSV);
            g_h1[b * DECD + i] = (mt_ > 0.f) ? hn : ho;
            g_h1res[b * DECD + i] = (pr - mean) * inv * P.ln1g[i] + P.ln1b[i];
        }
        gsync(ls);

        // ===== P4: gi2 (48 tiles)
        if (vid0 < 48) {
            int nt = vid0 >> 2, kc = vid0 & 3;
            gemm_tile(g_h1res, 0, 1, nullptr, DECD, P.g2wih, DECD, nullptr,
                      p_gi2 + kc * BATCH * 1536, 1536, 1536, 0,
                      0, nt * 128, kc * 128, 8, &G[half], barid, ltid);
        }
        gsync(ls);

        // ===== P5: gru2 + residual + LN2
        if (bid < BATCH) {
            const int b = bid, i = tid;
            const float mt_ = (t < s_dl[b]) ? 1.f : 0.f;
            float gir = P.g2bih[i], giz = P.g2bih[512 + i], gnn = P.g2bih[1024 + i];
#pragma unroll
            for (int c = 0; c < 4; c++) {
                int o = c * BATCH * 1536 + b * 1536;
                gir += p_gi2[o + i]; giz += p_gi2[o + 512 + i]; gnn += p_gi2[o + 1024 + i];
            }
            float ghr = P.g2bhh[i], ghz = P.g2bhh[512 + i], ghn = P.g2bhh[1024 + i];
#pragma unroll
            for (int c = 0; c < 4; c++) {
                int o = c * BATCH * 1536 + b * 1536;
                ghr += p_gh2[o + i]; ghz += p_gh2[o + 512 + i]; ghn += p_gh2[o + 1024 + i];
            }
            float r = sigm(gir + ghr), z = sigm(giz + ghz);
            float n = tanhf(gnn + r * ghn);
            float ho = g_h2[b * DECD + i];
            float hn = (1.f - z) * n + z * ho;
            float pr = hn + g_h1res[b * DECD + i];
            float sum  = bsum(pr, A->red);
            float sum2 = bsum(pr * pr, A->red);
            float mean = sum * (1.f / 512.f);
            float var  = sum2 * (1.f / 512.f) - mean * mean;
            float inv  = rsqrtf(var + EPSV);
            g_h2[b * DECD + i] = (mt_ > 0.f) ? hn : ho;
            g_h2res[b * DECD + i] = (pr - mean) * inv * P.ln2g[i] + P.ln2b[i];
        }
        gsync(ls);

        // ===== P6: ffn1 (32 tiles)
        if (vid0 < 32) {
            int nt = vid0 >> 2, kc = vid0 & 3;
            gemm_tile(g_h2res, 0, 1, nullptr, DECD, P.fw1, DECD, nullptr,
                      p_f1 + kc * BATCH * FFND, FFND, FFND, 0,
                      0, nt * 128, kc * 128, 8, &G[half], barid, ltid);
        }
        gsync(ls);

        // ===== P7: ffn2 (128) + att2-next (4) + gg-next (4)
        {
            int v = vid0;
            if (v < 128) {
                int nt = v >> 3, kc = v & 7;
                gemm_tile(p_f1, BATCH * FFND, 4, P.fb1, FFND, P.fw2, FFND, nullptr,
                          p_f2 + kc * BATCH * VOCAB, VOCAB, VOCAB, 0,
                          0, nt * 128, kc * 128, 8, &G[half], barid, ltid);
            } else if (v < 132) {
                int kc = v - 128;
                gemm_tile(g_h2, 0, 1, nullptr, DECD, P.daw, DECD, nullptr,
                          p_att2 + kc * BATCH * ATTD, ATTD, ATTD, 0,
                          0, 0, kc * 128, 8, &G[half], barid, ltid);
            } else if (v < 136) {
                int kc = v - 132;
                gemm_tile(g_h2, 0, 1, nullptr, DECD, P.gw1, DECD, nullptr,
                          p_gg + kc * BATCH * ATTD, ATTD, ATTD, 0,
                          0, 0, kc * 128, 8, &G[half], barid, ltid);
            }
        }
        gsync(ls);
    }

    // epilogue: pred-write t = 158
    for (int i = bid * NTHR + tid; i < BATCH * VOCAB; i += NBLK * NTHR) {
        int b = i / VOCAB, n = i - b * VOCAB;
        float m = (158 < s_dl[b]) ? 1.f : 0.f;
        float val = P.fb2[n];
#pragma unroll
        for (int c = 0; c < 8; c++) val += p_f2[c * BATCH * VOCAB + i];
        P.out[OP_OFF + ((size_t)b * TT + 158) * VOCAB + n] = val * m;
    }
}

// ---------------- host ----------------
extern "C" void kernel_launch(void* const* d_in, const int* in_sizes, int n_in,
                              void* d_out, int out_size) {
    (void)in_sizes; (void)n_in; (void)out_size;
    Params p;
    p.enc   = (const float*)d_in[0];
    p.caps  = (const int*)d_in[1];
    p.lens  = (const int*)d_in[2];
    p.eaw   = (const float*)d_in[3];
    p.eab   = (const float*)d_in[4];
    p.daw   = (const float*)d_in[5];
    p.dab   = (const float*)d_in[6];
    p.faw   = (const float*)d_in[7];
    p.fab   = (const float*)d_in[8];
    p.gw1   = (const float*)d_in[9];
    p.gb1   = (const float*)d_in[10];
    p.gw2   = (const float*)d_in[11];
    p.gb2   = (const float*)d_in[12];
    p.emb   = (const float*)d_in[13];
    p.g1wih = (const float*)d_in[14];
    p.g1whh = (const float*)d_in[15];
    p.g1bih = (const float*)d_in[16];
    p.g1bhh = (const float*)d_in[17];
    p.g2wih = (const float*)d_in[18];
    p.g2whh = (const float*)d_in[19];
    p.g2bih = (const float*)d_in[20];
    p.g2bhh = (const float*)d_in[21];
    p.pw    = (const float*)d_in[22];
    p.pb    = (const float*)d_in[23];
    p.ln1g  = (const float*)d_in[24];
    p.ln1b  = (const float*)d_in[25];
    p.ln2g  = (const float*)d_in[26];
    p.ln2b  = (const float*)d_in[27];
    p.fw1   = (const float*)d_in[28];
    p.fb1   = (const float*)d_in[29];
    p.fw2   = (const float*)d_in[30];
    p.fb2   = (const float*)d_in[31];
    p.out   = (float*)d_out;

    const int smem = 2 * (int)sizeof(SmemG) + (int)sizeof(SmemA);
    cudaFuncSetAttribute(decoder_persist, cudaFuncAttributeMaxDynamicSharedMemorySize, smem);
    decoder_persist<<<NBLK, NTHR, smem>>>(p);
}